// round 2
// baseline (speedup 1.0000x reference)
#include <cuda_runtime.h>
#include <cstdint>

#define GMAX 64
#define BMAX 16

__global__ void ssd_target_kernel(const float* __restrict__ gt,
                                  const int*   __restrict__ cls,
                                  const float* __restrict__ anchors,
                                  float*       __restrict__ out,
                                  int B, int A)
{
    __shared__ float4 s_box [BMAX * GMAX];   // y1,x1,y2,x2
    __shared__ float4 s_meta[BMAX * GMAX];   // gcy,gcx,log2(gh),log2(gw)
    __shared__ float  s_area[BMAX * GMAX];
    __shared__ float  s_cls [BMAX * GMAX];
    __shared__ int    s_cnt [BMAX];

    const int wid  = threadIdx.x >> 5;
    const int lane = threadIdx.x & 31;
    const int nw   = blockDim.x >> 5;

    // ---- per-batch order-preserving compaction of valid GTs (warp ballot) ----
    for (int b = wid; b < B; b += nw) {
        const int base = b * GMAX;
        int cnt = 0;
        #pragma unroll
        for (int chunk = 0; chunk < GMAX / 32; ++chunk) {
            const int g = chunk * 32 + lane;
            const float* gp = gt + (size_t)(base + g) * 5;
            float y1 = gp[0], x1 = gp[1], y2 = gp[2], x2 = gp[3], tg = gp[4];
            bool valid = (tg != 0.0f);
            unsigned m = __ballot_sync(0xffffffffu, valid);
            int pos = cnt + __popc(m & ((1u << lane) - 1u));
            if (valid) {
                s_box [base + pos] = make_float4(y1, x1, y2, x2);
                s_area[base + pos] = __fmul_rn(__fsub_rn(x2, x1), __fsub_rn(y2, y1));
                s_meta[base + pos] = make_float4((y2 + y1) * 0.5f, (x2 + x1) * 0.5f,
                                                 log2f(y2 - y1), log2f(x2 - x1));
                s_cls [base + pos] = (float)cls[(size_t)(base + g) * 2];
            }
            cnt += __popc(m);
        }
        if (lane == 0) {
            s_cnt[b] = cnt;
            if (cnt == 0) {
                // reference: argmax over all -1 == index 0; deltas built from raw gt[0]
                const float* gp = gt + (size_t)base * 5;
                float y1 = gp[0], x1 = gp[1], y2 = gp[2], x2 = gp[3];
                s_box [base] = make_float4(y1, x1, y2, x2);
                s_area[base] = __fmul_rn(__fsub_rn(x2, x1), __fsub_rn(y2, y1));
                s_meta[base] = make_float4((y2 + y1) * 0.5f, (x2 + x1) * 0.5f,
                                           log2f(y2 - y1), log2f(x2 - x1));
                s_cls [base] = (float)cls[(size_t)base * 2];
            }
        }
    }
    __syncthreads();

    const int a = blockIdx.x * blockDim.x + threadIdx.x;
    if (a >= A) return;

    // ---- per-anchor derived quantities (amortized over all B batches) ----
    const float4 an = __ldg(reinterpret_cast<const float4*>(anchors) + a);
    const float ay1 = an.x, ax1 = an.y, ay2 = an.z, ax2 = an.w;
    const float area_an = __fmul_rn(__fsub_rn(ax2, ax1), __fsub_rn(ay2, ay1));
    const float ah = ay2 - ay1, aw = ax2 - ax1;
    const float acy = (ay2 + ay1) * 0.5f, acx = (ax2 + ax1) * 0.5f;
    const float invh10 = 10.0f / ah;        // folds the /0.1 BBOX_STD
    const float invw10 = 10.0f / aw;
    const float lgah = log2f(ah), lgaw = log2f(aw);
    const float KLOG = 3.4657359027997265f; // ln(2) / 0.2  (folds the /0.2 BBOX_STD)

    const size_t N = (size_t)B * (size_t)A;
    float4* out4 = reinterpret_cast<float4*>(out); // deltas region [0, 4N)
    float*  outc = out + 4 * N;                    // class ids     [4N, 5N)
    float*  outt = out + 5 * N;                    // anchor tags   [5N, 6N)

    for (int b = 0; b < B; ++b) {
        const int base = b * GMAX;
        const int cnt  = s_cnt[b];
        float best_iou = -1.0f;
        int   bj = 0;
        // Exact-rounding IoU (matches jnp fp32 op-for-op) -> identical argmax / thresholds
        #pragma unroll 4
        for (int j = 0; j < cnt; ++j) {
            float4 g4 = s_box[base + j];
            float iw = fmaxf(0.0f, __fsub_rn(fminf(g4.w, ax2), fmaxf(g4.y, ax1)));
            float ih = fmaxf(0.0f, __fsub_rn(fminf(g4.z, ay2), fmaxf(g4.x, ay1)));
            float inter = __fmul_rn(iw, ih);
            float u = __fsub_rn(__fadd_rn(s_area[base + j], area_an), inter);
            float iou = __fdiv_rn(inter, u);
            if (iou > best_iou) { best_iou = iou; bj = j; }
        }
        const float4 mt = s_meta[base + bj];
        const float  cv = s_cls [base + bj];
        const float tagv = (best_iou >= 0.5f) ? 1.0f
                          : ((best_iou < 0.4f) ? -1.0f : 0.0f);
        const float dy = (mt.x - acy) * invh10;
        const float dx = (mt.y - acx) * invw10;
        const float dh = (mt.z - lgah) * KLOG;
        const float dw = (mt.w - lgaw) * KLOG;

        const size_t idx = (size_t)b * (size_t)A + (size_t)a;
        out4[idx] = make_float4(dy, dx, dh, dw);
        outc[idx] = cv;
        outt[idx] = tagv;
    }
}

extern "C" void kernel_launch(void* const* d_in, const int* in_sizes, int n_in,
                              void* d_out, int out_size)
{
    const float* gt      = (const float*)d_in[0];   // [B, 64, 5]
    const int*   cls     = (const int*)  d_in[1];   // [B, 64, 2]
    const float* anchors = (const float*)d_in[2];   // [A, 4]
    float* out = (float*)d_out;

    const int A = in_sizes[2] / 4;
    int B = in_sizes[0] / (GMAX * 5);
    if (B > BMAX) B = BMAX;

    const int threads = 128;
    const int blocks  = (A + threads - 1) / threads;
    ssd_target_kernel<<<blocks, threads>>>(gt, cls, anchors, out, B, A);
}

// round 3
// speedup vs baseline: 2.9460x; 2.9460x over previous
#include <cuda_runtime.h>
#include <cstdint>

#define GMAX   64
#define BGROUP 4

__global__ void ssd_target_kernel(const float* __restrict__ gt,
                                  const int*   __restrict__ cls,
                                  const float* __restrict__ anchors,
                                  float*       __restrict__ out,
                                  int B, int A)
{
    __shared__ float4 s_box [BGROUP * GMAX];   // y1,x1,y2,x2
    __shared__ float4 s_meta[BGROUP * GMAX];   // gcy,gcx,log2(gh),log2(gw)
    __shared__ float  s_area[BGROUP * GMAX];
    __shared__ float  s_cls [BGROUP * GMAX];
    __shared__ int    s_cnt [BGROUP];

    const int wid  = threadIdx.x >> 5;
    const int lane = threadIdx.x & 31;
    const int nw   = blockDim.x >> 5;

    const int b0 = blockIdx.y * BGROUP;                 // first batch of this group
    const int nb = min(BGROUP, B - b0);                 // batches handled here

    // ---- per-batch order-preserving compaction of valid GTs (warp ballot) ----
    for (int lb = wid; lb < nb; lb += nw) {
        const int gbase = (b0 + lb) * GMAX;             // global GT base
        const int sbase = lb * GMAX;                    // smem base
        int cnt = 0;
        #pragma unroll
        for (int chunk = 0; chunk < GMAX / 32; ++chunk) {
            const int g = chunk * 32 + lane;
            const float* gp = gt + (size_t)(gbase + g) * 5;
            float y1 = gp[0], x1 = gp[1], y2 = gp[2], x2 = gp[3], tg = gp[4];
            bool valid = (tg != 0.0f);
            unsigned m = __ballot_sync(0xffffffffu, valid);
            int pos = cnt + __popc(m & ((1u << lane) - 1u));
            if (valid) {
                s_box [sbase + pos] = make_float4(y1, x1, y2, x2);
                s_area[sbase + pos] = __fmul_rn(__fsub_rn(x2, x1), __fsub_rn(y2, y1));
                s_meta[sbase + pos] = make_float4((y2 + y1) * 0.5f, (x2 + x1) * 0.5f,
                                                  log2f(y2 - y1), log2f(x2 - x1));
                s_cls [sbase + pos] = (float)cls[(size_t)(gbase + g) * 2];
            }
            cnt += __popc(m);
        }
        if (lane == 0) {
            s_cnt[lb] = cnt;
            if (cnt == 0) {
                // reference: argmax over all -1 == index 0; deltas from raw gt[0]
                const float* gp = gt + (size_t)gbase * 5;
                float y1 = gp[0], x1 = gp[1], y2 = gp[2], x2 = gp[3];
                s_box [sbase] = make_float4(y1, x1, y2, x2);
                s_area[sbase] = __fmul_rn(__fsub_rn(x2, x1), __fsub_rn(y2, y1));
                s_meta[sbase] = make_float4((y2 + y1) * 0.5f, (x2 + x1) * 0.5f,
                                            log2f(y2 - y1), log2f(x2 - x1));
                s_cls [sbase] = (float)cls[(size_t)gbase * 2];
            }
        }
    }
    __syncthreads();

    const int a = blockIdx.x * blockDim.x + threadIdx.x;
    if (a >= A) return;

    // ---- per-anchor derived quantities (amortized over BGROUP batches) ----
    const float4 an = __ldg(reinterpret_cast<const float4*>(anchors) + a);
    const float ay1 = an.x, ax1 = an.y, ay2 = an.z, ax2 = an.w;
    const float area_an = __fmul_rn(__fsub_rn(ax2, ax1), __fsub_rn(ay2, ay1));
    const float ah = ay2 - ay1, aw = ax2 - ax1;
    const float acy = (ay2 + ay1) * 0.5f, acx = (ax2 + ax1) * 0.5f;
    const float invh10 = 10.0f / ah;          // folds /0.1 BBOX_STD
    const float invw10 = 10.0f / aw;
    const float lgah = log2f(ah), lgaw = log2f(aw);
    const float KLOG = 3.4657359027997265f;   // ln(2)/0.2 (folds /0.2 BBOX_STD)

    const size_t N = (size_t)B * (size_t)A;
    float4* out4 = reinterpret_cast<float4*>(out); // deltas  [0, 4N)
    float*  outc = out + 4 * N;                    // classes [4N, 5N)
    float*  outt = out + 5 * N;                    // tags    [5N, 6N)

    for (int lb = 0; lb < nb; ++lb) {
        const int sbase = lb * GMAX;
        const int cnt   = s_cnt[lb];

        // Division-free argmax: iou_j > iou_best  <=>  inter_j*u_best > inter_best*u_j
        float binter = -1.0f;   // "iou = -1" sentinel: -1/1
        float bu     =  1.0f;
        int   bj     =  0;
        #pragma unroll 4
        for (int j = 0; j < cnt; ++j) {
            float4 g4 = s_box[sbase + j];
            float iw = fmaxf(0.0f, __fsub_rn(fminf(g4.w, ax2), fmaxf(g4.y, ax1)));
            float ih = fmaxf(0.0f, __fsub_rn(fminf(g4.z, ay2), fmaxf(g4.x, ay1)));
            float inter = __fmul_rn(iw, ih);
            float u = __fsub_rn(__fadd_rn(s_area[sbase + j], area_an), inter);
            bool better = __fmul_rn(inter, bu) > __fmul_rn(binter, u);
            binter = better ? inter : binter;
            bu     = better ? u     : bu;
            bj     = better ? j     : bj;
        }

        // Single correctly-rounded division for the winner (bit-matches jnp iou_max)
        const float iou_max = __fdiv_rn(binter, bu);
        const float tagv = (iou_max >= 0.5f) ? 1.0f
                          : ((iou_max < 0.4f) ? -1.0f : 0.0f);

        const float4 mt = s_meta[sbase + bj];
        const float  cv = s_cls [sbase + bj];
        const float dy = (mt.x - acy) * invh10;
        const float dx = (mt.y - acx) * invw10;
        const float dh = (mt.z - lgah) * KLOG;
        const float dw = (mt.w - lgaw) * KLOG;

        const size_t idx = (size_t)(b0 + lb) * (size_t)A + (size_t)a;
        out4[idx] = make_float4(dy, dx, dh, dw);
        outc[idx] = cv;
        outt[idx] = tagv;
    }
}

extern "C" void kernel_launch(void* const* d_in, const int* in_sizes, int n_in,
                              void* d_out, int out_size)
{
    const float* gt      = (const float*)d_in[0];   // [B, 64, 5]
    const int*   cls     = (const int*)  d_in[1];   // [B, 64, 2]
    const float* anchors = (const float*)d_in[2];   // [A, 4]
    float* out = (float*)d_out;

    const int A = in_sizes[2] / 4;
    const int B = in_sizes[0] / (GMAX * 5);

    const int threads = 128;
    dim3 grid((A + threads - 1) / threads, (B + BGROUP - 1) / BGROUP);
    ssd_target_kernel<<<grid, threads>>>(gt, cls, anchors, out, B, A);
}

// round 4
// speedup vs baseline: 3.1909x; 1.0831x over previous
#include <cuda_runtime.h>
#include <cstdint>

#define GMAX   64
#define BGROUP 2
#define ANCH   2
#define NTHR   128

__global__ void __launch_bounds__(NTHR)
ssd_target_kernel(const float* __restrict__ gt,
                  const int*   __restrict__ cls,
                  const float* __restrict__ anchors,
                  float*       __restrict__ out,
                  int B, int A)
{
    __shared__ float4 s_box [BGROUP * GMAX];   // y1,x1,y2,x2
    __shared__ float4 s_meta[BGROUP * GMAX];   // gcy,gcx,log2(gh),log2(gw)
    __shared__ float  s_area[BGROUP * GMAX];
    __shared__ float  s_cls [BGROUP * GMAX];
    __shared__ int    s_cnt [BGROUP];

    const int wid  = threadIdx.x >> 5;
    const int lane = threadIdx.x & 31;
    const int nw   = blockDim.x >> 5;

    const int b0 = blockIdx.y * BGROUP;
    const int nb = min(BGROUP, B - b0);

    // ---- per-batch order-preserving compaction of valid GTs (warp ballot) ----
    for (int lb = wid; lb < nb; lb += nw) {
        const int gbase = (b0 + lb) * GMAX;
        const int sbase = lb * GMAX;
        int cnt = 0;
        #pragma unroll
        for (int chunk = 0; chunk < GMAX / 32; ++chunk) {
            const int g = chunk * 32 + lane;
            const float* gp = gt + (size_t)(gbase + g) * 5;
            float y1 = gp[0], x1 = gp[1], y2 = gp[2], x2 = gp[3], tg = gp[4];
            bool valid = (tg != 0.0f);
            unsigned m = __ballot_sync(0xffffffffu, valid);
            int pos = cnt + __popc(m & ((1u << lane) - 1u));
            if (valid) {
                s_box [sbase + pos] = make_float4(y1, x1, y2, x2);
                s_area[sbase + pos] = __fmul_rn(__fsub_rn(x2, x1), __fsub_rn(y2, y1));
                s_meta[sbase + pos] = make_float4((y2 + y1) * 0.5f, (x2 + x1) * 0.5f,
                                                  log2f(y2 - y1), log2f(x2 - x1));
                s_cls [sbase + pos] = (float)cls[(size_t)(gbase + g) * 2];
            }
            cnt += __popc(m);
        }
        if (lane == 0) {
            s_cnt[lb] = cnt;
            if (cnt == 0) {
                // reference: argmax over all -1 == index 0; deltas from raw gt[0]
                const float* gp = gt + (size_t)gbase * 5;
                float y1 = gp[0], x1 = gp[1], y2 = gp[2], x2 = gp[3];
                s_box [sbase] = make_float4(y1, x1, y2, x2);
                s_area[sbase] = __fmul_rn(__fsub_rn(x2, x1), __fsub_rn(y2, y1));
                s_meta[sbase] = make_float4((y2 + y1) * 0.5f, (x2 + x1) * 0.5f,
                                            log2f(y2 - y1), log2f(x2 - x1));
                s_cls [sbase] = (float)cls[(size_t)gbase * 2];
            }
        }
    }
    __syncthreads();

    const int a0 = blockIdx.x * (NTHR * ANCH) + threadIdx.x;
    const int a1 = a0 + NTHR;
    if (a0 >= A) return;
    const bool has1 = (a1 < A);

    const float4 an0 = __ldg(reinterpret_cast<const float4*>(anchors) + a0);
    const float4 an1 = has1 ? __ldg(reinterpret_cast<const float4*>(anchors) + a1) : an0;
    const float area0 = __fmul_rn(__fsub_rn(an0.w, an0.y), __fsub_rn(an0.z, an0.x));
    const float area1 = __fmul_rn(__fsub_rn(an1.w, an1.y), __fsub_rn(an1.z, an1.x));

    const size_t N = (size_t)B * (size_t)A;
    float4* out4 = reinterpret_cast<float4*>(out); // deltas  [0, 4N)
    float*  outc = out + 4 * N;                    // classes [4N, 5N)
    float*  outt = out + 5 * N;                    // tags    [5N, 6N)
    const float KLOG = 3.4657359027997265f;        // ln(2)/0.2 (folds /0.2 BBOX_STD)

    for (int lb = 0; lb < nb; ++lb) {
        const int sbase = lb * GMAX;
        const int cnt   = s_cnt[lb];

        // Division- and union-free argmax:
        //   iou_j > iou_b  <=>  inter_j * S_b > inter_b * S_j,  S = area_gt + area_an
        // (inter*inter cross terms cancel exactly; S,u > 0)
        float bi0 = -1.0f, bS0 = 0.0f; int bj0 = 0;   // sentinel: iou = -1/(0-(-1)) = -1
        float bi1 = -1.0f, bS1 = 0.0f; int bj1 = 0;

        #pragma unroll 4
        for (int j = 0; j < cnt; ++j) {
            const float4 g4 = s_box [sbase + j];
            const float  ag = s_area[sbase + j];

            // anchor 0
            {
                float iw = fmaxf(0.0f, __fsub_rn(fminf(g4.w, an0.w), fmaxf(g4.y, an0.y)));
                float ih = fmaxf(0.0f, __fsub_rn(fminf(g4.z, an0.z), fmaxf(g4.x, an0.x)));
                float inter = __fmul_rn(iw, ih);
                float S = __fadd_rn(ag, area0);
                bool better = __fmul_rn(inter, bS0) > __fmul_rn(bi0, S);
                bi0 = better ? inter : bi0;
                bS0 = better ? S     : bS0;
                bj0 = better ? j     : bj0;
            }
            // anchor 1 (independent chain — ILP)
            {
                float iw = fmaxf(0.0f, __fsub_rn(fminf(g4.w, an1.w), fmaxf(g4.y, an1.y)));
                float ih = fmaxf(0.0f, __fsub_rn(fminf(g4.z, an1.z), fmaxf(g4.x, an1.x)));
                float inter = __fmul_rn(iw, ih);
                float S = __fadd_rn(ag, area1);
                bool better = __fmul_rn(inter, bS1) > __fmul_rn(bi1, S);
                bi1 = better ? inter : bi1;
                bS1 = better ? S     : bS1;
                bj1 = better ? j     : bj1;
            }
        }

        const size_t row = (size_t)(b0 + lb) * (size_t)A;

        // ---- epilogue anchor 0 ----
        {
            // winner union with reference rounding: u = (area_gt + area_an) - inter
            const float iou_max = __fdiv_rn(bi0, __fsub_rn(bS0, bi0));
            const float tagv = (iou_max >= 0.5f) ? 1.0f
                              : ((iou_max < 0.4f) ? -1.0f : 0.0f);
            const float4 mt = s_meta[sbase + bj0];
            const float ah = an0.z - an0.x, aw = an0.w - an0.y;
            const float acy = (an0.z + an0.x) * 0.5f, acx = (an0.w + an0.y) * 0.5f;
            const float dy = (mt.x - acy) * (10.0f / ah);
            const float dx = (mt.y - acx) * (10.0f / aw);
            const float dh = (mt.z - log2f(ah)) * KLOG;
            const float dw = (mt.w - log2f(aw)) * KLOG;
            const size_t idx = row + (size_t)a0;
            out4[idx] = make_float4(dy, dx, dh, dw);
            outc[idx] = s_cls[sbase + bj0];
            outt[idx] = tagv;
        }
        // ---- epilogue anchor 1 ----
        if (has1) {
            const float iou_max = __fdiv_rn(bi1, __fsub_rn(bS1, bi1));
            const float tagv = (iou_max >= 0.5f) ? 1.0f
                              : ((iou_max < 0.4f) ? -1.0f : 0.0f);
            const float4 mt = s_meta[sbase + bj1];
            const float ah = an1.z - an1.x, aw = an1.w - an1.y;
            const float acy = (an1.z + an1.x) * 0.5f, acx = (an1.w + an1.y) * 0.5f;
            const float dy = (mt.x - acy) * (10.0f / ah);
            const float dx = (mt.y - acx) * (10.0f / aw);
            const float dh = (mt.z - log2f(ah)) * KLOG;
            const float dw = (mt.w - log2f(aw)) * KLOG;
            const size_t idx = row + (size_t)a1;
            out4[idx] = make_float4(dy, dx, dh, dw);
            outc[idx] = s_cls[sbase + bj1];
            outt[idx] = tagv;
        }
    }
}

extern "C" void kernel_launch(void* const* d_in, const int* in_sizes, int n_in,
                              void* d_out, int out_size)
{
    const float* gt      = (const float*)d_in[0];   // [B, 64, 5]
    const int*   cls     = (const int*)  d_in[1];   // [B, 64, 2]
    const float* anchors = (const float*)d_in[2];   // [A, 4]
    float* out = (float*)d_out;

    const int A = in_sizes[2] / 4;
    const int B = in_sizes[0] / (GMAX * 5);

    dim3 grid((A + NTHR * ANCH - 1) / (NTHR * ANCH), (B + BGROUP - 1) / BGROUP);
    ssd_target_kernel<<<grid, NTHR>>>(gt, cls, anchors, out, B, A);
}

// round 5
// speedup vs baseline: 3.2629x; 1.0226x over previous
#include <cuda_runtime.h>
#include <cstdint>

#define GMAX   64
#define BGROUP 2
#define ANCH   2
#define NTHR   128

__global__ void __launch_bounds__(NTHR, 12)
ssd_target_kernel(const float* __restrict__ gt,
                  const int*   __restrict__ cls,
                  const float* __restrict__ anchors,
                  float*       __restrict__ out,
                  int B, int A)
{
    __shared__ float4 s_box [BGROUP * GMAX];   // y1,x1,y2,x2
    __shared__ float4 s_meta[BGROUP * GMAX];   // gcy,gcx,log2(gh),log2(gw)
    __shared__ float  s_area[BGROUP * GMAX];
    __shared__ float  s_cls [BGROUP * GMAX];
    __shared__ int    s_cnt [BGROUP];

    const int wid  = threadIdx.x >> 5;
    const int lane = threadIdx.x & 31;
    const int nw   = blockDim.x >> 5;

    const int b0 = blockIdx.y * BGROUP;
    const int nb = min(BGROUP, B - b0);

    // ---- per-batch order-preserving compaction of valid GTs (warp ballot) ----
    for (int lb = wid; lb < nb; lb += nw) {
        const int gbase = (b0 + lb) * GMAX;
        const int sbase = lb * GMAX;
        int cnt = 0;
        #pragma unroll
        for (int chunk = 0; chunk < GMAX / 32; ++chunk) {
            const int g = chunk * 32 + lane;
            const float* gp = gt + (size_t)(gbase + g) * 5;
            float y1 = gp[0], x1 = gp[1], y2 = gp[2], x2 = gp[3], tg = gp[4];
            bool valid = (tg != 0.0f);
            unsigned m = __ballot_sync(0xffffffffu, valid);
            int pos = cnt + __popc(m & ((1u << lane) - 1u));
            if (valid) {
                s_box [sbase + pos] = make_float4(y1, x1, y2, x2);
                s_area[sbase + pos] = __fmul_rn(__fsub_rn(x2, x1), __fsub_rn(y2, y1));
                s_meta[sbase + pos] = make_float4((y2 + y1) * 0.5f, (x2 + x1) * 0.5f,
                                                  log2f(y2 - y1), log2f(x2 - x1));
                s_cls [sbase + pos] = (float)cls[(size_t)(gbase + g) * 2];
            }
            cnt += __popc(m);
        }
        if (lane == 0) {
            s_cnt[lb] = cnt;
            if (cnt == 0) {
                // reference: argmax over all -1 == index 0; deltas from raw gt[0]
                const float* gp = gt + (size_t)gbase * 5;
                float y1 = gp[0], x1 = gp[1], y2 = gp[2], x2 = gp[3];
                s_box [sbase] = make_float4(y1, x1, y2, x2);
                s_area[sbase] = __fmul_rn(__fsub_rn(x2, x1), __fsub_rn(y2, y1));
                s_meta[sbase] = make_float4((y2 + y1) * 0.5f, (x2 + x1) * 0.5f,
                                            log2f(y2 - y1), log2f(x2 - x1));
                s_cls [sbase] = (float)cls[(size_t)gbase * 2];
            }
        }
    }
    __syncthreads();

    const int a0 = blockIdx.x * (NTHR * ANCH) + threadIdx.x;
    const int a1 = a0 + NTHR;
    if (a0 >= A) return;
    const bool has1 = (a1 < A);

    const float4 an0 = __ldg(reinterpret_cast<const float4*>(anchors) + a0);
    const float4 an1 = has1 ? __ldg(reinterpret_cast<const float4*>(anchors) + a1) : an0;
    const float area0 = __fmul_rn(__fsub_rn(an0.w, an0.y), __fsub_rn(an0.z, an0.x));
    const float area1 = __fmul_rn(__fsub_rn(an1.w, an1.y), __fsub_rn(an1.z, an1.x));

    const size_t N = (size_t)B * (size_t)A;
    float4* out4 = reinterpret_cast<float4*>(out); // deltas  [0, 4N)
    float*  outc = out + 4 * N;                    // classes [4N, 5N)
    float*  outt = out + 5 * N;                    // tags    [5N, 6N)
    const float KLOG = 3.4657359027997265f;        // ln(2)/0.2 (folds /0.2 BBOX_STD)

    for (int lb = 0; lb < nb; ++lb) {
        const int sbase = lb * GMAX;
        const int cnt   = s_cnt[lb];

        // Division- and union-free argmax:
        //   iou_j > iou_b  <=>  inter_j * S_b > inter_b * S_j,  S = area_gt + area_an
        // (inter*inter cross terms cancel exactly; S,u > 0)
        // max(0,x) == __saturatef(x) here: all extents < 1, so the upper clamp
        // never fires and .SAT folds into the subtract (frees the FMNMX).
        float bi0 = -1.0f, bS0 = 0.0f; int bj0 = 0;   // sentinel: iou = -1/(0-(-1)) = -1
        float bi1 = -1.0f, bS1 = 0.0f; int bj1 = 0;

        #pragma unroll 4
        for (int j = 0; j < cnt; ++j) {
            const float4 g4 = s_box [sbase + j];
            const float  ag = s_area[sbase + j];

            // anchor 0
            {
                float iw = __saturatef(__fsub_rn(fminf(g4.w, an0.w), fmaxf(g4.y, an0.y)));
                float ih = __saturatef(__fsub_rn(fminf(g4.z, an0.z), fmaxf(g4.x, an0.x)));
                float inter = __fmul_rn(iw, ih);
                float S = __fadd_rn(ag, area0);
                bool better = __fmul_rn(inter, bS0) > __fmul_rn(bi0, S);
                bi0 = better ? inter : bi0;
                bS0 = better ? S     : bS0;
                bj0 = better ? j     : bj0;
            }
            // anchor 1 (independent chain — ILP)
            {
                float iw = __saturatef(__fsub_rn(fminf(g4.w, an1.w), fmaxf(g4.y, an1.y)));
                float ih = __saturatef(__fsub_rn(fminf(g4.z, an1.z), fmaxf(g4.x, an1.x)));
                float inter = __fmul_rn(iw, ih);
                float S = __fadd_rn(ag, area1);
                bool better = __fmul_rn(inter, bS1) > __fmul_rn(bi1, S);
                bi1 = better ? inter : bi1;
                bS1 = better ? S     : bS1;
                bj1 = better ? j     : bj1;
            }
        }

        const size_t row = (size_t)(b0 + lb) * (size_t)A;

        // ---- epilogue anchor 0 ----
        {
            // winner union with reference rounding: u = (area_gt + area_an) - inter
            const float iou_max = __fdiv_rn(bi0, __fsub_rn(bS0, bi0));
            const float tagv = (iou_max >= 0.5f) ? 1.0f
                              : ((iou_max < 0.4f) ? -1.0f : 0.0f);
            const float4 mt = s_meta[sbase + bj0];
            const float ah = an0.z - an0.x, aw = an0.w - an0.y;
            const float acy = (an0.z + an0.x) * 0.5f, acx = (an0.w + an0.y) * 0.5f;
            const float dy = (mt.x - acy) * (10.0f / ah);
            const float dx = (mt.y - acx) * (10.0f / aw);
            const float dh = (mt.z - log2f(ah)) * KLOG;
            const float dw = (mt.w - log2f(aw)) * KLOG;
            const size_t idx = row + (size_t)a0;
            out4[idx] = make_float4(dy, dx, dh, dw);
            outc[idx] = s_cls[sbase + bj0];
            outt[idx] = tagv;
        }
        // ---- epilogue anchor 1 ----
        if (has1) {
            const float iou_max = __fdiv_rn(bi1, __fsub_rn(bS1, bi1));
            const float tagv = (iou_max >= 0.5f) ? 1.0f
                              : ((iou_max < 0.4f) ? -1.0f : 0.0f);
            const float4 mt = s_meta[sbase + bj1];
            const float ah = an1.z - an1.x, aw = an1.w - an1.y;
            const float acy = (an1.z + an1.x) * 0.5f, acx = (an1.w + an1.y) * 0.5f;
            const float dy = (mt.x - acy) * (10.0f / ah);
            const float dx = (mt.y - acx) * (10.0f / aw);
            const float dh = (mt.z - log2f(ah)) * KLOG;
            const float dw = (mt.w - log2f(aw)) * KLOG;
            const size_t idx = row + (size_t)a1;
            out4[idx] = make_float4(dy, dx, dh, dw);
            outc[idx] = s_cls[sbase + bj1];
            outt[idx] = tagv;
        }
    }
}

extern "C" void kernel_launch(void* const* d_in, const int* in_sizes, int n_in,
                              void* d_out, int out_size)
{
    const float* gt      = (const float*)d_in[0];   // [B, 64, 5]
    const int*   cls     = (const int*)  d_in[1];   // [B, 64, 2]
    const float* anchors = (const float*)d_in[2];   // [A, 4]
    float* out = (float*)d_out;

    const int A = in_sizes[2] / 4;
    const int B = in_sizes[0] / (GMAX * 5);

    dim3 grid((A + NTHR * ANCH - 1) / (NTHR * ANCH), (B + BGROUP - 1) / BGROUP);
    ssd_target_kernel<<<grid, NTHR>>>(gt, cls, anchors, out, B, A);
}

// round 6
// speedup vs baseline: 3.4172x; 1.0473x over previous
#include <cuda_runtime.h>
#include <cstdint>

#define GMAX   64
#define BGROUP 4
#define NTHR   128

__global__ void __launch_bounds__(NTHR, 14)
ssd_target_kernel(const float* __restrict__ gt,
                  const int*   __restrict__ cls,
                  const float* __restrict__ anchors,
                  float*       __restrict__ out,
                  int B, int A)
{
    __shared__ float4 s_box [BGROUP * GMAX];   // y1,x1,y2,x2
    __shared__ float4 s_meta[BGROUP * GMAX];   // gcy,gcx,log2(gh),log2(gw)
    __shared__ float  s_area[BGROUP * GMAX];
    __shared__ float  s_cls [BGROUP * GMAX];
    __shared__ int    s_cnt [BGROUP];

    const int wid  = threadIdx.x >> 5;
    const int lane = threadIdx.x & 31;
    const int nw   = blockDim.x >> 5;

    const int b0 = blockIdx.y * BGROUP;
    const int nb = min(BGROUP, B - b0);

    // ---- per-batch order-preserving compaction of valid GTs (warp ballot) ----
    for (int lb = wid; lb < nb; lb += nw) {
        const int gbase = (b0 + lb) * GMAX;
        const int sbase = lb * GMAX;
        int cnt = 0;
        #pragma unroll
        for (int chunk = 0; chunk < GMAX / 32; ++chunk) {
            const int g = chunk * 32 + lane;
            const float* gp = gt + (size_t)(gbase + g) * 5;
            float y1 = gp[0], x1 = gp[1], y2 = gp[2], x2 = gp[3], tg = gp[4];
            bool valid = (tg != 0.0f);
            unsigned m = __ballot_sync(0xffffffffu, valid);
            int pos = cnt + __popc(m & ((1u << lane) - 1u));
            if (valid) {
                s_box [sbase + pos] = make_float4(y1, x1, y2, x2);
                s_area[sbase + pos] = __fmul_rn(__fsub_rn(x2, x1), __fsub_rn(y2, y1));
                s_meta[sbase + pos] = make_float4((y2 + y1) * 0.5f, (x2 + x1) * 0.5f,
                                                  log2f(y2 - y1), log2f(x2 - x1));
                s_cls [sbase + pos] = (float)cls[(size_t)(gbase + g) * 2];
            }
            cnt += __popc(m);
        }
        if (lane == 0) {
            s_cnt[lb] = cnt;
            if (cnt == 0) {
                // reference: argmax over all -1 == index 0; deltas from raw gt[0]
                const float* gp = gt + (size_t)gbase * 5;
                float y1 = gp[0], x1 = gp[1], y2 = gp[2], x2 = gp[3];
                s_box [sbase] = make_float4(y1, x1, y2, x2);
                s_area[sbase] = __fmul_rn(__fsub_rn(x2, x1), __fsub_rn(y2, y1));
                s_meta[sbase] = make_float4((y2 + y1) * 0.5f, (x2 + x1) * 0.5f,
                                            log2f(y2 - y1), log2f(x2 - x1));
                s_cls [sbase] = (float)cls[(size_t)gbase * 2];
            }
        }
    }
    __syncthreads();

    const int a = blockIdx.x * NTHR + threadIdx.x;
    if (a >= A) return;

    // ---- per-anchor derived quantities, hoisted across ALL batches ----
    const float4 an = __ldg(reinterpret_cast<const float4*>(anchors) + a);
    const float area_an = __fmul_rn(__fsub_rn(an.w, an.y), __fsub_rn(an.z, an.x));
    const float ah = an.z - an.x, aw = an.w - an.y;
    const float acy = (an.z + an.x) * 0.5f, acx = (an.w + an.y) * 0.5f;
    const float invh10 = 10.0f / ah;           // folds /0.1 BBOX_STD
    const float invw10 = 10.0f / aw;
    const float lgah = log2f(ah), lgaw = log2f(aw);
    const float KLOG = 3.4657359027997265f;    // ln(2)/0.2 (folds /0.2 BBOX_STD)

    const size_t N = (size_t)B * (size_t)A;
    float4* out4 = reinterpret_cast<float4*>(out); // deltas  [0, 4N)
    float*  outc = out + 4 * N;                    // classes [4N, 5N)
    float*  outt = out + 5 * N;                    // tags    [5N, 6N)

    for (int lb = 0; lb < nb; ++lb) {
        const int sbase = lb * GMAX;
        const int cnt   = s_cnt[lb];

        // Division/union-free argmax with pairwise tournament (halved chain depth):
        //   iou_j > iou_b  <=>  inter_j * S_b > inter_b * S_j,  S = area_gt + area_an
        // max(0,x)==__saturatef(x) here (all extents < 1) -> .SAT folds into the FADD.
        float bi = -1.0f, bS = 0.0f; int bj = 0;   // sentinel: iou = -1/(0-(-1)) = -1
        int j = 0;
        for (; j + 1 < cnt; j += 2) {
            const float4 gA = s_box [sbase + j];
            const float agA = s_area[sbase + j];
            float iwA = __saturatef(__fsub_rn(fminf(gA.w, an.w), fmaxf(gA.y, an.y)));
            float ihA = __saturatef(__fsub_rn(fminf(gA.z, an.z), fmaxf(gA.x, an.x)));
            float iA  = __fmul_rn(iwA, ihA);
            float SA  = __fadd_rn(agA, area_an);

            const float4 gB = s_box [sbase + j + 1];
            const float agB = s_area[sbase + j + 1];
            float iwB = __saturatef(__fsub_rn(fminf(gB.w, an.w), fmaxf(gB.y, an.y)));
            float ihB = __saturatef(__fsub_rn(fminf(gB.z, an.z), fmaxf(gB.x, an.x)));
            float iB  = __fmul_rn(iwB, ihB);
            float SB  = __fadd_rn(agB, area_an);

            // pair winner (strict >, earlier index on tie) — independent of running best
            bool pb = __fmul_rn(iB, SA) > __fmul_rn(iA, SB);
            float pi = pb ? iB : iA;
            float pS = pb ? SB : SA;
            int   pj = pb ? (j + 1) : j;

            // vs running best (strict >, earlier index on tie)
            bool better = __fmul_rn(pi, bS) > __fmul_rn(bi, pS);
            bi = better ? pi : bi;
            bS = better ? pS : bS;
            bj = better ? pj : bj;
        }
        if (j < cnt) {  // odd tail
            const float4 gA = s_box [sbase + j];
            const float agA = s_area[sbase + j];
            float iwA = __saturatef(__fsub_rn(fminf(gA.w, an.w), fmaxf(gA.y, an.y)));
            float ihA = __saturatef(__fsub_rn(fminf(gA.z, an.z), fmaxf(gA.x, an.x)));
            float iA  = __fmul_rn(iwA, ihA);
            float SA  = __fadd_rn(agA, area_an);
            bool better = __fmul_rn(iA, bS) > __fmul_rn(bi, SA);
            bi = better ? iA : bi;
            bS = better ? SA : bS;
            bj = better ? j  : bj;
        }

        // winner union with reference rounding: u = (area_gt + area_an) - inter
        const float iou_max = __fdiv_rn(bi, __fsub_rn(bS, bi));
        const float tagv = (iou_max >= 0.5f) ? 1.0f
                          : ((iou_max < 0.4f) ? -1.0f : 0.0f);
        const float4 mt = s_meta[sbase + bj];
        const float dy = (mt.x - acy) * invh10;
        const float dx = (mt.y - acx) * invw10;
        const float dh = (mt.z - lgah) * KLOG;
        const float dw = (mt.w - lgaw) * KLOG;

        const size_t idx = (size_t)(b0 + lb) * (size_t)A + (size_t)a;
        out4[idx] = make_float4(dy, dx, dh, dw);
        outc[idx] = s_cls[sbase + bj];
        outt[idx] = tagv;
    }
}

extern "C" void kernel_launch(void* const* d_in, const int* in_sizes, int n_in,
                              void* d_out, int out_size)
{
    const float* gt      = (const float*)d_in[0];   // [B, 64, 5]
    const int*   cls     = (const int*)  d_in[1];   // [B, 64, 2]
    const float* anchors = (const float*)d_in[2];   // [A, 4]
    float* out = (float*)d_out;

    const int A = in_sizes[2] / 4;
    const int B = in_sizes[0] / (GMAX * 5);

    dim3 grid((A + NTHR - 1) / NTHR, (B + BGROUP - 1) / BGROUP);
    ssd_target_kernel<<<grid, NTHR>>>(gt, cls, anchors, out, B, A);
}